// round 5
// baseline (speedup 1.0000x reference)
#include <cuda_runtime.h>
#include <cuda_bf16.h>

#define R_MAX 2.0f
#define DR_MIN 0.02f
#define PI_F 3.14159265358979323846f
#define NBLOCKS 148
#define NTHREADS 896

__device__ float g_partials[NBLOCKS];
__device__ unsigned int g_count = 0;

__global__ void __launch_bounds__(NTHREADS, 1)
exp_rep_kernel(const float* __restrict__ dr_vec,
               const int* __restrict__ Z,
               const int* __restrict__ idx_i,
               const int* __restrict__ idx_j,
               const float* __restrict__ rep_scale,
               const float* __restrict__ rep_prefactor,
               float* __restrict__ out,
               int n_edges, int n_atoms)
{
    extern __shared__ unsigned char smem[];
    float2* s_tab = (float2*)smem;              // 119 x {|A|, 1/|R|}
    unsigned char* s_Z = smem + 1024;           // n_atoms bytes (uint8 Z)

    int tid = threadIdx.x;
    if (tid < 119) {
        s_tab[tid] = make_float2(fabsf(rep_prefactor[tid]),
                                 1.0f / fabsf(rep_scale[tid]));
    }
    // stage Z (int32) -> smem uint8, vectorized
    int n4a = n_atoms >> 2;
    const int4* Z4 = (const int4*)Z;
    uchar4* sZ4 = (uchar4*)s_Z;
    for (int i = tid; i < n4a; i += NTHREADS) {
        int4 z = __ldg(Z4 + i);
        sZ4[i] = make_uchar4((unsigned char)z.x, (unsigned char)z.y,
                             (unsigned char)z.z, (unsigned char)z.w);
    }
    for (int i = (n4a << 2) + tid; i < n_atoms; i += NTHREADS)
        s_Z[i] = (unsigned char)Z[i];
    __syncthreads();

    float acc = 0.0f;
    int n_chunks = n_edges >> 2;
    int gstride = NBLOCKS * NTHREADS;
    const float4* dv4 = (const float4*)dr_vec;
    const int4*   I4  = (const int4*)idx_i;
    const int4*   J4  = (const int4*)idx_j;

    // ---- software pipeline: prefetch depth 1 ----
    int c = blockIdx.x * NTHREADS + tid;
    bool valid = (c < n_chunks);
    float4 va, vb, vc;
    int4 ii4, jj4;
    va = vb = vc = make_float4(0.f, 0.f, 0.f, 0.f);
    ii4 = jj4 = make_int4(0, 0, 0, 0);
    if (valid) {
        ii4 = __ldcs(I4 + c);
        jj4 = __ldcs(J4 + c);
        va  = __ldcs(dv4 + 3 * c + 0);
        vb  = __ldcs(dv4 + 3 * c + 1);
        vc  = __ldcs(dv4 + 3 * c + 2);
    }

    while (valid) {
        int cn = c + gstride;
        bool nvalid = (cn < n_chunks);
        float4 nva = va, nvb = vb, nvc = vc;
        int4 nii = ii4, njj = jj4;
        if (nvalid) {
            nii = __ldcs(I4 + cn);
            njj = __ldcs(J4 + cn);
            nva = __ldcs(dv4 + 3 * cn + 0);
            nvb = __ldcs(dv4 + 3 * cn + 1);
            nvc = __ldcs(dv4 + 3 * cn + 2);
        }

        // ---- compute current chunk ----
        float ex[4], ey[4], ez[4];
        ex[0] = va.x; ey[0] = va.y; ez[0] = va.z;
        ex[1] = va.w; ey[1] = vb.x; ez[1] = vb.y;
        ex[2] = vb.z; ey[2] = vb.w; ez[2] = vc.x;
        ex[3] = vc.y; ey[3] = vc.z; ez[3] = vc.w;
        int ii[4] = {ii4.x, ii4.y, ii4.z, ii4.w};
        int jj[4] = {jj4.x, jj4.y, jj4.z, jj4.w};

        int zi[4], zj[4];
        #pragma unroll
        for (int k = 0; k < 4; k++) {
            zi[k] = (int)s_Z[ii[k]];
            zj[k] = (int)s_Z[jj[k]];
        }
        float2 pi[4], pj[4];
        #pragma unroll
        for (int k = 0; k < 4; k++) {
            pi[k] = s_tab[zi[k]];
            pj[k] = s_tab[zj[k]];
        }

        #pragma unroll
        for (int k = 0; k < 4; k++) {
            float r2 = ex[k]*ex[k] + ey[k]*ey[k] + ez[k]*ez[k];
            float dr = sqrtf(r2);
            dr = fminf(fmaxf(dr, DR_MIN), R_MAX);
            // 0.5*(cos(pi*dr/R_MAX)+1) via MUFU.COS (fast path)
            float cosc = 0.5f * (__cosf(dr * (PI_F / R_MAX)) + 1.0f);
            float f = pi[k].x * pj[k].x * __expf(-dr * (pi[k].y + pj[k].y)) *
                      __fdividef(cosc, dr * dr);
            acc += (ii[k] != jj[k]) ? f : 0.0f;
        }

        // rotate pipeline
        c = cn; valid = nvalid;
        va = nva; vb = nvb; vc = nvc;
        ii4 = nii; jj4 = njj;
    }

    // remainder edges (n_edges % 4): block 0, thread 0
    if (blockIdx.x == 0 && tid == 0) {
        for (int e = n_chunks << 2; e < n_edges; e++) {
            float dx = dr_vec[3*e+0], dy = dr_vec[3*e+1], dz = dr_vec[3*e+2];
            int ii = idx_i[e], jj = idx_j[e];
            float2 pi = s_tab[(int)s_Z[ii]];
            float2 pj = s_tab[(int)s_Z[jj]];
            float dr = sqrtf(dx*dx + dy*dy + dz*dz);
            dr = fminf(fmaxf(dr, DR_MIN), R_MAX);
            float cosc = 0.5f * (__cosf(dr * (PI_F / R_MAX)) + 1.0f);
            float f = pi.x * pj.x * __expf(-dr * (pi.y + pj.y)) *
                      __fdividef(cosc, dr * dr);
            acc += (ii != jj) ? f : 0.0f;
        }
    }

    // warp reduce, block reduce, deterministic cross-block finish
    #pragma unroll
    for (int off = 16; off > 0; off >>= 1)
        acc += __shfl_down_sync(0xFFFFFFFF, acc, off);

    __shared__ float s_red[32];
    int warp = tid >> 5;
    if ((tid & 31) == 0) s_red[warp] = acc;
    __syncthreads();
    if (warp == 0) {
        float v = (tid < (NTHREADS / 32)) ? s_red[tid] : 0.0f;
        #pragma unroll
        for (int off = 16; off > 0; off >>= 1)
            v += __shfl_down_sync(0xFFFFFFFF, v, off);
        if (tid == 0) {
            g_partials[blockIdx.x] = v;
            __threadfence();
            unsigned int ticket = atomicAdd(&g_count, 1u);
            if (ticket == NBLOCKS - 1) {
                float s = 0.0f;
                #pragma unroll 4
                for (int i = 0; i < NBLOCKS; i++) s += g_partials[i];
                out[0] = s;
                g_count = 0;  // reset for next graph replay
            }
        }
    }
}

extern "C" void kernel_launch(void* const* d_in, const int* in_sizes, int n_in,
                              void* d_out, int out_size)
{
    const float* dr_vec        = (const float*)d_in[1];
    const int*   Z             = (const int*)d_in[2];
    const int*   idx           = (const int*)d_in[3];
    const float* rep_scale     = (const float*)d_in[6];
    const float* rep_prefactor = (const float*)d_in[7];
    float* out = (float*)d_out;

    int n_edges = in_sizes[1] / 3;
    int n_atoms = in_sizes[2];
    const int* idx_i = idx;
    const int* idx_j = idx + n_edges;

    int smem_bytes = 1024 + ((n_atoms + 127) & ~127);
    cudaFuncSetAttribute(exp_rep_kernel,
                         cudaFuncAttributeMaxDynamicSharedMemorySize, smem_bytes);

    exp_rep_kernel<<<NBLOCKS, NTHREADS, smem_bytes>>>(
        dr_vec, Z, idx_i, idx_j, rep_scale, rep_prefactor,
        out, n_edges, n_atoms);
}

// round 6
// speedup vs baseline: 1.0076x; 1.0076x over previous
#include <cuda_runtime.h>
#include <cuda_bf16.h>

#define R_MAX 2.0f
#define DR_MIN 0.02f
#define PI_F 3.14159265358979323846f
#define NBLOCKS 148
#define NTHREADS 1024

__device__ unsigned char g_Z8[204800];   // 200K atoms as u8 (16B aligned)
__device__ float g_partials[NBLOCKS];
__device__ unsigned int g_count = 0;

__global__ void z_to_u8_kernel(const int* __restrict__ Z, int n)
{
    int i = blockIdx.x * blockDim.x + threadIdx.x;  // one int4 = 4 atoms
    int n4 = n >> 2;
    if (i < n4) {
        int4 z = __ldg((const int4*)Z + i);
        ((uchar4*)g_Z8)[i] = make_uchar4((unsigned char)z.x, (unsigned char)z.y,
                                         (unsigned char)z.z, (unsigned char)z.w);
    }
    if (i == 0) {
        for (int k = n4 << 2; k < n; k++) g_Z8[k] = (unsigned char)Z[k];
    }
}

__global__ void __launch_bounds__(NTHREADS, 1)
exp_rep_kernel(const float* __restrict__ dr_vec,
               const int* __restrict__ idx_i,
               const int* __restrict__ idx_j,
               const float* __restrict__ rep_scale,
               const float* __restrict__ rep_prefactor,
               float* __restrict__ out,
               int n_edges, int n_atoms)
{
    extern __shared__ unsigned char smem[];
    float2* s_tab = (float2*)smem;              // 119 x {|A|, 1/|R|}
    unsigned char* s_Z = smem + 1024;           // n_atoms bytes (uint8 Z)

    int tid = threadIdx.x;
    if (tid < 119) {
        s_tab[tid] = make_float2(fabsf(rep_prefactor[tid]),
                                 1.0f / fabsf(rep_scale[tid]));
    }
    // stage u8 Z table -> smem, 16B at a time (200KB -> ~12 iters/thread)
    int n16 = n_atoms >> 4;
    const int4* gZ16 = (const int4*)g_Z8;
    int4* sZ16 = (int4*)s_Z;
    for (int i = tid; i < n16; i += NTHREADS)
        sZ16[i] = __ldg(gZ16 + i);
    for (int i = (n16 << 4) + tid; i < n_atoms; i += NTHREADS)
        s_Z[i] = g_Z8[i];
    __syncthreads();

    float acc = 0.0f;
    int n_chunks = n_edges >> 2;
    int gstride = NBLOCKS * NTHREADS;
    const float4* dv4 = (const float4*)dr_vec;
    const int4*   I4  = (const int4*)idx_i;
    const int4*   J4  = (const int4*)idx_j;

    // ---- software pipeline: prefetch depth 1 ----
    int c = blockIdx.x * NTHREADS + tid;
    bool valid = (c < n_chunks);
    float4 va, vb, vc;
    int4 ii4, jj4;
    va = vb = vc = make_float4(0.f, 0.f, 0.f, 0.f);
    ii4 = jj4 = make_int4(0, 0, 0, 0);
    if (valid) {
        ii4 = __ldcs(I4 + c);
        jj4 = __ldcs(J4 + c);
        va  = __ldcs(dv4 + 3 * c + 0);
        vb  = __ldcs(dv4 + 3 * c + 1);
        vc  = __ldcs(dv4 + 3 * c + 2);
    }

    while (valid) {
        int cn = c + gstride;
        bool nvalid = (cn < n_chunks);
        float4 nva = va, nvb = vb, nvc = vc;
        int4 nii = ii4, njj = jj4;
        if (nvalid) {
            nii = __ldcs(I4 + cn);
            njj = __ldcs(J4 + cn);
            nva = __ldcs(dv4 + 3 * cn + 0);
            nvb = __ldcs(dv4 + 3 * cn + 1);
            nvc = __ldcs(dv4 + 3 * cn + 2);
        }

        float ex[4], ey[4], ez[4];
        ex[0] = va.x; ey[0] = va.y; ez[0] = va.z;
        ex[1] = va.w; ey[1] = vb.x; ez[1] = vb.y;
        ex[2] = vb.z; ey[2] = vb.w; ez[2] = vc.x;
        ex[3] = vc.y; ey[3] = vc.z; ez[3] = vc.w;
        int ii[4] = {ii4.x, ii4.y, ii4.z, ii4.w};
        int jj[4] = {jj4.x, jj4.y, jj4.z, jj4.w};

        int zi[4], zj[4];
        #pragma unroll
        for (int k = 0; k < 4; k++) {
            zi[k] = (int)s_Z[ii[k]];
            zj[k] = (int)s_Z[jj[k]];
        }
        float2 pi[4], pj[4];
        #pragma unroll
        for (int k = 0; k < 4; k++) {
            pi[k] = s_tab[zi[k]];
            pj[k] = s_tab[zj[k]];
        }

        #pragma unroll
        for (int k = 0; k < 4; k++) {
            float r2 = ex[k]*ex[k] + ey[k]*ey[k] + ez[k]*ez[k];
            float dr = sqrtf(r2);
            dr = fminf(fmaxf(dr, DR_MIN), R_MAX);
            float cosc = 0.5f * (__cosf(dr * (PI_F / R_MAX)) + 1.0f);
            float inv = __frcp_rn(dr * dr);
            float f = pi[k].x * pj[k].x * __expf(-dr * (pi[k].y + pj[k].y)) *
                      cosc * inv;
            acc += (ii[k] != jj[k]) ? f : 0.0f;
        }

        c = cn; valid = nvalid;
        va = nva; vb = nvb; vc = nvc;
        ii4 = nii; jj4 = njj;
    }

    // remainder edges (n_edges % 4): block 0, thread 0
    if (blockIdx.x == 0 && tid == 0) {
        for (int e = n_chunks << 2; e < n_edges; e++) {
            float dx = dr_vec[3*e+0], dy = dr_vec[3*e+1], dz = dr_vec[3*e+2];
            int ii = idx_i[e], jj = idx_j[e];
            float2 pi = s_tab[(int)s_Z[ii]];
            float2 pj = s_tab[(int)s_Z[jj]];
            float dr = sqrtf(dx*dx + dy*dy + dz*dz);
            dr = fminf(fmaxf(dr, DR_MIN), R_MAX);
            float cosc = 0.5f * (__cosf(dr * (PI_F / R_MAX)) + 1.0f);
            float f = pi.x * pj.x * __expf(-dr * (pi.y + pj.y)) *
                      cosc * __frcp_rn(dr * dr);
            acc += (ii != jj) ? f : 0.0f;
        }
    }

    // warp reduce, block reduce, deterministic cross-block finish
    #pragma unroll
    for (int off = 16; off > 0; off >>= 1)
        acc += __shfl_down_sync(0xFFFFFFFF, acc, off);

    __shared__ float s_red[32];
    int warp = tid >> 5;
    if ((tid & 31) == 0) s_red[warp] = acc;
    __syncthreads();
    if (warp == 0) {
        float v = (tid < (NTHREADS / 32)) ? s_red[tid] : 0.0f;
        #pragma unroll
        for (int off = 16; off > 0; off >>= 1)
            v += __shfl_down_sync(0xFFFFFFFF, v, off);
        if (tid == 0) {
            g_partials[blockIdx.x] = v;
            __threadfence();
            unsigned int ticket = atomicAdd(&g_count, 1u);
            if (ticket == NBLOCKS - 1) {
                float s = 0.0f;
                #pragma unroll 4
                for (int i = 0; i < NBLOCKS; i++) s += g_partials[i];
                out[0] = s;
                g_count = 0;  // reset for next graph replay
            }
        }
    }
}

extern "C" void kernel_launch(void* const* d_in, const int* in_sizes, int n_in,
                              void* d_out, int out_size)
{
    const float* dr_vec        = (const float*)d_in[1];
    const int*   Z             = (const int*)d_in[2];
    const int*   idx           = (const int*)d_in[3];
    const float* rep_scale     = (const float*)d_in[6];
    const float* rep_prefactor = (const float*)d_in[7];
    float* out = (float*)d_out;

    int n_edges = in_sizes[1] / 3;
    int n_atoms = in_sizes[2];
    const int* idx_i = idx;
    const int* idx_j = idx + n_edges;

    int n4 = n_atoms >> 2;
    z_to_u8_kernel<<<(n4 + 255) / 256, 256>>>(Z, n_atoms);

    int smem_bytes = 1024 + ((n_atoms + 15) & ~15);
    cudaFuncSetAttribute(exp_rep_kernel,
                         cudaFuncAttributeMaxDynamicSharedMemorySize, smem_bytes);

    exp_rep_kernel<<<NBLOCKS, NTHREADS, smem_bytes>>>(
        dr_vec, idx_i, idx_j, rep_scale, rep_prefactor,
        out, n_edges, n_atoms);
}